// round 4
// baseline (speedup 1.0000x reference)
#include <cuda_runtime.h>
#include <math.h>

typedef unsigned long long ull;

#define NB 4
#define NV 16384
#define NK 16
#define NE 32
#define ND 64
#define NH 4
#define NL 2
#define NEGV (-1e9f)
#define NODES (NB * NV)

// ---------------- scratch ----------------
__device__ float g_h[NODES * ND];
__device__ float g_t[(size_t)NODES * NH * ND];
__device__ float g_zscr[NODES * ND];
__device__ float g_ssrc[NODES * NH];
__device__ float g_sdst[NODES * NH];
__device__ float g_m[NODES * ND];
__device__ float g_nodew[NODES];
__device__ float g_sn[NODES];
__device__ float g_inflowA[NODES];
__device__ float g_inflowB[NODES];

__device__ __forceinline__ float sigmoidf_(float x) { return 1.0f / (1.0f + expf(-x)); }

__device__ __forceinline__ ull pack2(float x) {
    ull r; asm("mov.b64 %0, {%1, %1};" : "=l"(r) : "f"(x)); return r;
}
__device__ __forceinline__ ull packf2(float a, float b) {
    ull r; asm("mov.b64 %0, {%1, %2};" : "=l"(r) : "f"(a), "f"(b)); return r;
}
__device__ __forceinline__ void ffma2(ull& d, ull a, ull b) {
    asm("fma.rn.f32x2 %0, %1, %2, %0;" : "+l"(d) : "l"(a), "l"(b));
}
__device__ __forceinline__ float2 unpk(ull v) {
    float2 f; asm("mov.b64 {%0, %1}, %2;" : "=f"(f.x), "=f"(f.y) : "l"(v)); return f;
}
__device__ __forceinline__ void st4(float* p, float a, float b, float c, float d) {
    *reinterpret_cast<float4*>(p) = make_float4(a, b, c, d);
}

// stage 128 node rows of 64 floats TRANSPOSED into xs[64][128] (thread = node)
__device__ __forceinline__ void stage_xT(const float* __restrict__ g, float* xs) {
    int tid = threadIdx.x;
    const float4* g4 = reinterpret_cast<const float4*>(g + (size_t)tid * ND);
#pragma unroll
    for (int c = 0; c < 16; c++) {
        float4 v = __ldg(g4 + c);
        xs[(4 * c + 0) * 128 + tid] = v.x;
        xs[(4 * c + 1) * 128 + tid] = v.y;
        xs[(4 * c + 2) * 128 + tid] = v.z;
        xs[(4 * c + 3) * 128 + tid] = v.w;
    }
}

// register-tiled pass: acc[j*4+p] (cols tc8+j, node-pair p) += xs^T @ Wg (W from global via L1)
template <int K>
__device__ __forceinline__ void gpass_g(const float* __restrict__ xs, const float* __restrict__ Wg,
                                        ull acc[32], int tn8, int tc8) {
#pragma unroll 4
    for (int k = 0; k < K; k++) {
        const ulonglong2* xr = reinterpret_cast<const ulonglong2*>(xs + k * 128 + tn8);
        ulonglong2 xa = xr[0], xb = xr[1];
        const float4* wr = reinterpret_cast<const float4*>(Wg + k * ND + tc8);
        float4 wa = __ldg(wr), wb = __ldg(wr + 1);
        ull w0 = pack2(wa.x), w1 = pack2(wa.y), w2 = pack2(wa.z), w3 = pack2(wa.w);
        ull w4 = pack2(wb.x), w5 = pack2(wb.y), w6 = pack2(wb.z), w7 = pack2(wb.w);
#define FFJ(j, wv)                    \
    ffma2(acc[(j)*4 + 0], wv, xa.x);  \
    ffma2(acc[(j)*4 + 1], wv, xa.y);  \
    ffma2(acc[(j)*4 + 2], wv, xb.x);  \
    ffma2(acc[(j)*4 + 3], wv, xb.y);
        FFJ(0, w0) FFJ(1, w1) FFJ(2, w2) FFJ(3, w3)
        FFJ(4, w4) FFJ(5, w5) FFJ(6, w6) FFJ(7, w7)
#undef FFJ
    }
}

__device__ __forceinline__ void acc_bias(ull acc[32], const float* __restrict__ b, int tc8) {
#pragma unroll
    for (int j = 0; j < 8; j++) {
        ull v = pack2(__ldg(&b[tc8 + j]));
        acc[j * 4 + 0] = v; acc[j * 4 + 1] = v; acc[j * 4 + 2] = v; acc[j * 4 + 3] = v;
    }
}
__device__ __forceinline__ void acc_zero(ull acc[32]) {
#pragma unroll
    for (int i = 0; i < 32; i++) acc[i] = 0ull;
}

// ---------------- encoder ----------------
#define ENC_SMEM ((34 * 128 + 64 * 128) * 4)
__global__ void __launch_bounds__(128, 3)
k_encoder(const float* __restrict__ emb, const float* __restrict__ feat,
          const float* __restrict__ W1, const float* __restrict__ b1,
          const float* __restrict__ W2, const float* __restrict__ b2) {
    extern __shared__ float sm[];
    float* xs1 = sm;                // [34][128]
    float* xs2 = sm + 34 * 128;     // [64][128]
    int tid = threadIdx.x;
    int nb0 = blockIdx.x * 128;
    int tn8 = (tid >> 3) * 8, tc8 = (tid & 7) * 8;

    {
        const float4* e4 = reinterpret_cast<const float4*>(emb + (size_t)(nb0 + tid) * NE);
#pragma unroll
        for (int c = 0; c < 8; c++) {
            float4 v = __ldg(e4 + c);
            xs1[(4 * c + 0) * 128 + tid] = v.x;
            xs1[(4 * c + 1) * 128 + tid] = v.y;
            xs1[(4 * c + 2) * 128 + tid] = v.z;
            xs1[(4 * c + 3) * 128 + tid] = v.w;
        }
        float2 fv = __ldg(reinterpret_cast<const float2*>(feat + (size_t)(nb0 + tid) * 2));
        xs1[32 * 128 + tid] = fv.x;
        xs1[33 * 128 + tid] = fv.y;
    }
    g_inflowA[nb0 + tid] = 0.0f;
    g_inflowB[nb0 + tid] = 0.0f;
    __syncthreads();

    ull acc[32];
    acc_bias(acc, b1, tc8);
    gpass_g<34>(xs1, W1, acc, tn8, tc8);
#pragma unroll
    for (int j = 0; j < 8; j++)
#pragma unroll
        for (int p = 0; p < 4; p++) {
            float2 v = unpk(acc[j * 4 + p]);
            *reinterpret_cast<ull*>(xs2 + (tc8 + j) * 128 + tn8 + 2 * p) =
                packf2(tanhf(v.x), tanhf(v.y));
        }
    __syncthreads();

    acc_bias(acc, b2, tc8);
    gpass_g<64>(xs2, W2, acc, tn8, tc8);
#pragma unroll
    for (int p = 0; p < 4; p++) {
        float o0[8], o1[8];
#pragma unroll
        for (int j = 0; j < 8; j++) {
            float2 v = unpk(acc[j * 4 + p]);
            o0[j] = tanhf(v.x); o1[j] = tanhf(v.y);
        }
        float* r0 = g_h + (size_t)(nb0 + tn8 + 2 * p) * ND + tc8;
        st4(r0, o0[0], o0[1], o0[2], o0[3]); st4(r0 + 4, o0[4], o0[5], o0[6], o0[7]);
        float* r1 = r0 + ND;
        st4(r1, o1[0], o1[1], o1[2], o1[3]); st4(r1 + 4, o1[4], o1[5], o1[6], o1[7]);
    }
}

// ---------------- GAT transform ----------------
#define GAT_SMEM (64 * 128 * 4)
__global__ void __launch_bounds__(128, 3)
k_gat_t(const float* __restrict__ Wgat, const float* __restrict__ asrc,
        const float* __restrict__ adst) {
    extern __shared__ float sm[];
    float* xs = sm;  // [64][128]
    int tid = threadIdx.x;
    int nb0 = blockIdx.x * 128;
    int tn8 = (tid >> 3) * 8, tc8 = (tid & 7) * 8;
    stage_xT(g_h + (size_t)nb0 * ND, xs);
    __syncthreads();

    for (int hd = 0; hd < NH; hd++) {
        ull acc[32];
        acc_zero(acc);
        gpass_g<64>(xs, Wgat + (size_t)hd * ND * ND, acc, tn8, tc8);

        float as_[8], ad_[8];
#pragma unroll
        for (int j = 0; j < 8; j++) {
            as_[j] = __ldg(&asrc[hd * ND + tc8 + j]);
            ad_[j] = __ldg(&adst[hd * ND + tc8 + j]);
        }
        float ss8[8], sd8[8];
#pragma unroll
        for (int p = 0; p < 4; p++) {
            float o0[8], o1[8];
            float s0 = 0.f, s1 = 0.f, d0 = 0.f, d1 = 0.f;
#pragma unroll
            for (int j = 0; j < 8; j++) {
                float2 v = unpk(acc[j * 4 + p]);
                o0[j] = v.x; o1[j] = v.y;
                s0 += v.x * as_[j]; d0 += v.x * ad_[j];
                s1 += v.y * as_[j]; d1 += v.y * ad_[j];
            }
            float* t0 = g_t + ((size_t)(nb0 + tn8 + 2 * p) * NH + hd) * ND + tc8;
            st4(t0, o0[0], o0[1], o0[2], o0[3]); st4(t0 + 4, o0[4], o0[5], o0[6], o0[7]);
            float* t1 = t0 + NH * ND;
            st4(t1, o1[0], o1[1], o1[2], o1[3]); st4(t1 + 4, o1[4], o1[5], o1[6], o1[7]);
            ss8[2 * p] = s0; ss8[2 * p + 1] = s1;
            sd8[2 * p] = d0; sd8[2 * p + 1] = d1;
        }
#pragma unroll
        for (int q = 0; q < 8; q++) {
#pragma unroll
            for (int off = 4; off > 0; off >>= 1) {
                ss8[q] += __shfl_xor_sync(0xffffffffu, ss8[q], off);
                sd8[q] += __shfl_xor_sync(0xffffffffu, sd8[q], off);
            }
        }
        if ((tid & 7) == 0) {
#pragma unroll
            for (int q = 0; q < 8; q++) {
                g_ssrc[(size_t)(nb0 + tn8 + q) * NH + hd] = ss8[q];
                g_sdst[(size_t)(nb0 + tn8 + q) * NH + hd] = sd8[q];
            }
        }
    }
}

// ---------------- GAT attention + aggregation ----------------
__global__ void k_gat_attn(const int* __restrict__ adj) {
    __shared__ float s_agg[4][NH][ND];
    int wid = threadIdx.x >> 5, lane = threadIdx.x & 31;
    int ni = wid >> 2, hd = wid & 3;
    int n = (blockIdx.x << 2) + ni;
    int b = n >> 14;

    float score = NEGV;
    int idx = NV;
    if (lane < NK) {
        idx = __ldg(&adj[(size_t)n * NK + lane]);
        if (idx < NV)
            score = __ldg(&g_ssrc[(size_t)n * NH + hd]) +
                    __ldg(&g_sdst[((size_t)(b << 14) + idx) * NH + hd]);
    }
    float mx = score;
#pragma unroll
    for (int o = 16; o > 0; o >>= 1) mx = fmaxf(mx, __shfl_xor_sync(0xffffffffu, mx, o));
    float e = (lane < NK) ? expf(score - mx) : 0.0f;
    float s = e;
#pragma unroll
    for (int o = 16; o > 0; o >>= 1) s += __shfl_xor_sync(0xffffffffu, s, o);
    float attn = e / s;

    float ax = 0.0f, ay = 0.0f;
#pragma unroll
    for (int k = 0; k < NK; k++) {
        int j = __shfl_sync(0xffffffffu, idx, k);
        float a = __shfl_sync(0xffffffffu, attn, k);
        if (j < NV) {
            const float2* tp =
                reinterpret_cast<const float2*>(g_t + (((size_t)(b << 14) + j) * NH + hd) * ND);
            float2 tv = __ldg(tp + lane);
            ax += a * tv.x; ay += a * tv.y;
        }
    }
    s_agg[ni][hd][2 * lane] = ax;
    s_agg[ni][hd][2 * lane + 1] = ay;
    __syncthreads();
    if (threadIdx.x < 256) {
        int nn = threadIdx.x >> 6, j = threadIdx.x & 63;
        float t = s_agg[nn][0][j] + s_agg[nn][1][j] + s_agg[nn][2][j] + s_agg[nn][3][j];
        g_m[((size_t)(blockIdx.x << 2) + nn) * ND + j] = tanhf(t * 0.25f);
    }
}

// ---------------- fused GRU (z -> scratch, r*h overwrites xh, c + combine) ----------------
#define GRU_SMEM (2 * 64 * 128 * 4)
__global__ void __launch_bounds__(128, 3)
k_gru(const float* __restrict__ Wz, const float* __restrict__ Uz, const float* __restrict__ bz,
      const float* __restrict__ Wr, const float* __restrict__ Ur, const float* __restrict__ br,
      const float* __restrict__ Wc, const float* __restrict__ Uc, const float* __restrict__ bc) {
    extern __shared__ float sm[];
    float* xm = sm;             // [64][128]
    float* xh = sm + 64 * 128;  // [64][128], later holds r*h
    int tid = threadIdx.x;
    int nb0 = blockIdx.x * 128;
    int tn8 = (tid >> 3) * 8, tc8 = (tid & 7) * 8;

    stage_xT(g_m + (size_t)nb0 * ND, xm);
    stage_xT(g_h + (size_t)nb0 * ND, xh);
    __syncthreads();

    ull acc[32];
    // ---- z -> global scratch ----
    acc_bias(acc, bz, tc8);
    gpass_g<64>(xm, Wz, acc, tn8, tc8);
    gpass_g<64>(xh, Uz, acc, tn8, tc8);
#pragma unroll
    for (int p = 0; p < 4; p++) {
        float o0[8], o1[8];
#pragma unroll
        for (int j = 0; j < 8; j++) {
            float2 v = unpk(acc[j * 4 + p]);
            o0[j] = sigmoidf_(v.x); o1[j] = sigmoidf_(v.y);
        }
        float* r0 = g_zscr + (size_t)(nb0 + tn8 + 2 * p) * ND + tc8;
        st4(r0, o0[0], o0[1], o0[2], o0[3]); st4(r0 + 4, o0[4], o0[5], o0[6], o0[7]);
        float* r1 = r0 + ND;
        st4(r1, o1[0], o1[1], o1[2], o1[3]); st4(r1 + 4, o1[4], o1[5], o1[6], o1[7]);
    }
    // ---- r, r*h -> xh (in place) ----
    acc_bias(acc, br, tc8);
    gpass_g<64>(xm, Wr, acc, tn8, tc8);
    gpass_g<64>(xh, Ur, acc, tn8, tc8);
    ull rh[32];
#pragma unroll
    for (int j = 0; j < 8; j++)
#pragma unroll
        for (int p = 0; p < 4; p++) {
            float2 rv = unpk(acc[j * 4 + p]);
            float2 hv = unpk(*reinterpret_cast<const ull*>(xh + (tc8 + j) * 128 + tn8 + 2 * p));
            rh[j * 4 + p] = packf2(sigmoidf_(rv.x) * hv.x, sigmoidf_(rv.y) * hv.y);
        }
    __syncthreads();
#pragma unroll
    for (int j = 0; j < 8; j++)
#pragma unroll
        for (int p = 0; p < 4; p++)
            *reinterpret_cast<ull*>(xh + (tc8 + j) * 128 + tn8 + 2 * p) = rh[j * 4 + p];
    __syncthreads();
    // ---- c + combine ----
    acc_bias(acc, bc, tc8);
    gpass_g<64>(xm, Wc, acc, tn8, tc8);
    gpass_g<64>(xh, Uc, acc, tn8, tc8);
#pragma unroll
    for (int p = 0; p < 4; p++) {
        float* hr0 = g_h + (size_t)(nb0 + tn8 + 2 * p) * ND + tc8;
        float* hr1 = hr0 + ND;
        const float* zr0 = g_zscr + (size_t)(nb0 + tn8 + 2 * p) * ND + tc8;
        const float* zr1 = zr0 + ND;
        float4 h0a = *reinterpret_cast<const float4*>(hr0);
        float4 h0b = *reinterpret_cast<const float4*>(hr0 + 4);
        float4 h1a = *reinterpret_cast<const float4*>(hr1);
        float4 h1b = *reinterpret_cast<const float4*>(hr1 + 4);
        float4 z0a = __ldg(reinterpret_cast<const float4*>(zr0));
        float4 z0b = __ldg(reinterpret_cast<const float4*>(zr0 + 4));
        float4 z1a = __ldg(reinterpret_cast<const float4*>(zr1));
        float4 z1b = __ldg(reinterpret_cast<const float4*>(zr1 + 4));
        float c0[8], c1[8];
#pragma unroll
        for (int j = 0; j < 8; j++) {
            float2 v = unpk(acc[j * 4 + p]);
            c0[j] = tanhf(v.x); c1[j] = tanhf(v.y);
        }
        st4(hr0, h0a.x + z0a.x * (c0[0] - h0a.x), h0a.y + z0a.y * (c0[1] - h0a.y),
                 h0a.z + z0a.z * (c0[2] - h0a.z), h0a.w + z0a.w * (c0[3] - h0a.w));
        st4(hr0 + 4, h0b.x + z0b.x * (c0[4] - h0b.x), h0b.y + z0b.y * (c0[5] - h0b.y),
                     h0b.z + z0b.z * (c0[6] - h0b.z), h0b.w + z0b.w * (c0[7] - h0b.w));
        st4(hr1, h1a.x + z1a.x * (c1[0] - h1a.x), h1a.y + z1a.y * (c1[1] - h1a.y),
                 h1a.z + z1a.z * (c1[2] - h1a.z), h1a.w + z1a.w * (c1[3] - h1a.w));
        st4(hr1 + 4, h1b.x + z1b.x * (c1[4] - h1b.x), h1b.y + z1b.y * (c1[5] - h1b.y),
                     h1b.z + z1b.z * (c1[6] - h1b.z), h1b.w + z1b.w * (c1[7] - h1b.w));
    }
}

// ---------------- decoder ----------------
#define DEC_SMEM (64 * 128 * 4)
__global__ void __launch_bounds__(128, 3)
k_decoder(const float* __restrict__ W1, const float* __restrict__ b1,
          const float* __restrict__ W2, const float* __restrict__ b2) {
    extern __shared__ float sm[];
    float* xs = sm;
    int tid = threadIdx.x;
    int nb0 = blockIdx.x * 128;
    int tn8 = (tid >> 3) * 8, tc8 = (tid & 7) * 8;
    stage_xT(g_h + (size_t)nb0 * ND, xs);
    __syncthreads();
    ull acc[32];
    acc_bias(acc, b1, tc8);
    gpass_g<64>(xs, W1, acc, tn8, tc8);
    float w2_[8];
#pragma unroll
    for (int j = 0; j < 8; j++) w2_[j] = __ldg(&W2[tc8 + j]);
    float pw[8];
#pragma unroll
    for (int p = 0; p < 4; p++) {
        float s0 = 0.f, s1 = 0.f;
#pragma unroll
        for (int j = 0; j < 8; j++) {
            float2 v = unpk(acc[j * 4 + p]);
            s0 += tanhf(v.x) * w2_[j];
            s1 += tanhf(v.y) * w2_[j];
        }
        pw[2 * p] = s0; pw[2 * p + 1] = s1;
    }
#pragma unroll
    for (int q = 0; q < 8; q++)
#pragma unroll
        for (int off = 4; off > 0; off >>= 1)
            pw[q] += __shfl_xor_sync(0xffffffffu, pw[q], off);
    if ((tid & 7) == 0) {
        float b2v = __ldg(&b2[0]);
#pragma unroll
        for (int q = 0; q < 8; q++) g_nodew[nb0 + tn8 + q] = pw[q] + b2v;
    }
}

// ---------------- edge softmax + sumsq + flow0 scatter ----------------
__global__ void k_normw(const int* __restrict__ adj, const float* __restrict__ demands,
                        float* __restrict__ out_normw) {
    int n = blockIdx.x * blockDim.x + threadIdx.x;
    int b = n >> 14;
    int base = b << 14;
    int idxv[NK];
    float sc[NK];
    float mx = NEGV;
#pragma unroll
    for (int k = 0; k < NK; k++) {
        int idx = __ldg(&adj[(size_t)n * NK + k]);
        idxv[k] = idx;
        float s = (idx < NV) ? __ldg(&g_nodew[(size_t)base + idx]) : NEGV;
        sc[k] = s;
        mx = fmaxf(mx, s);
    }
    float sum = 0.0f;
#pragma unroll
    for (int k = 0; k < NK; k++) { sc[k] = expf(sc[k] - mx); sum += sc[k]; }
    float inv = 1.0f / sum;
    float nf0 = fmaxf(-__ldg(&demands[n]), 0.0f);
    float sn = 0.0f;
#pragma unroll
    for (int k = 0; k < NK; k++) {
        float nw = sc[k] * inv;
        sc[k] = nw;
        sn += nw * nw;
        out_normw[(size_t)n * NK + k] = nw;
    }
    g_sn[n] = sn;
#pragma unroll
    for (int k = 0; k < NK; k++)
        if (idxv[k] < NV) atomicAdd(&g_inflowA[base + idxv[k]], sc[k] * nf0);
}

// ---------------- fused flow iteration ----------------
__global__ void k_flow_iter(const int* __restrict__ adj, const float* __restrict__ demands,
                            const float* __restrict__ normw, float* __restrict__ cur,
                            float* __restrict__ nxt, float* __restrict__ store) {
    int n = blockIdx.x * blockDim.x + threadIdx.x;
    int base = (n >> 14) << 14;
    float nf = fmaxf(cur[n] - __ldg(&demands[n]), 0.0f);
    cur[n] = 0.0f;
#pragma unroll
    for (int k = 0; k < NK; k++) {
        int idx = __ldg(&adj[(size_t)n * NK + k]);
        float f = __ldg(&normw[(size_t)n * NK + k]) * nf;
        if (store) store[(size_t)n * NK + k] = f;
        if (idx < NV) atomicAdd(&nxt[base + idx], f);
    }
}

// ---------------- final flow + cost ----------------
__global__ void k_flow_last(const float* __restrict__ demands, const float* __restrict__ normw,
                            float* __restrict__ cur, float* __restrict__ out_flow,
                            float* __restrict__ cost) {
    int n = blockIdx.x * blockDim.x + threadIdx.x;
    int b = n >> 14;
    float nf = fmaxf(cur[n] - __ldg(&demands[n]), 0.0f);
    cur[n] = 0.0f;
    const float4* nw4 = reinterpret_cast<const float4*>(normw + (size_t)n * NK);
    float4* o4 = reinterpret_cast<float4*>(out_flow + (size_t)n * NK);
#pragma unroll
    for (int k = 0; k < 4; k++) {
        float4 v = __ldg(nw4 + k);
        v.x *= nf; v.y *= nf; v.z *= nf; v.w *= nf;
        o4[k] = v;
    }
    float val = nf * nf * __ldg(&g_sn[n]);
#pragma unroll
    for (int o = 16; o > 0; o >>= 1) val += __shfl_xor_sync(0xffffffffu, val, o);
    __shared__ float ws[8];
    if ((threadIdx.x & 31) == 0) ws[threadIdx.x >> 5] = val;
    __syncthreads();
    if (threadIdx.x == 0) {
        float t = 0.0f;
#pragma unroll
        for (int i = 0; i < 8; i++) t += ws[i];
        atomicAdd(&cost[b], t);
    }
}

// ---------------- launch ----------------
extern "C" void kernel_launch(void* const* d_in, const int* in_sizes, int n_in,
                              void* d_out, int out_size) {
    const float* emb     = (const float*)d_in[0];
    const float* feat    = (const float*)d_in[1];
    const float* demands = (const float*)d_in[2];
    const int*   adj     = (const int*)d_in[3];
    int wb = (in_sizes[5] == 1) ? 6 : 5;
    const float* W_enc1 = (const float*)d_in[wb + 0];
    const float* b_enc1 = (const float*)d_in[wb + 1];
    const float* W_enc2 = (const float*)d_in[wb + 2];
    const float* b_enc2 = (const float*)d_in[wb + 3];
    const float* W_gat  = (const float*)d_in[wb + 4];
    const float* a_src  = (const float*)d_in[wb + 5];
    const float* a_dst  = (const float*)d_in[wb + 6];
    const float* W_z    = (const float*)d_in[wb + 7];
    const float* U_z    = (const float*)d_in[wb + 8];
    const float* b_z    = (const float*)d_in[wb + 9];
    const float* W_r    = (const float*)d_in[wb + 10];
    const float* U_r    = (const float*)d_in[wb + 11];
    const float* b_r    = (const float*)d_in[wb + 12];
    const float* W_c    = (const float*)d_in[wb + 13];
    const float* U_c    = (const float*)d_in[wb + 14];
    const float* b_c    = (const float*)d_in[wb + 15];
    const float* W_dec1 = (const float*)d_in[wb + 16];
    const float* b_dec1 = (const float*)d_in[wb + 17];
    const float* W_dec2 = (const float*)d_in[wb + 18];
    const float* b_dec2 = (const float*)d_in[wb + 19];

    float* out = (float*)d_out;
    float* out_flow  = out;                               // [B,V,K] f10
    float* out_cost  = out + (size_t)NB * NV * NK;        // [B]
    float* out_normw = out_cost + NB;                     // [B,V,K]
    float* out_pflow = out_normw + (size_t)NB * NV * NK;  // [B,V,K] f9

    float *pA, *pB;
    cudaGetSymbolAddress((void**)&pA, g_inflowA);
    cudaGetSymbolAddress((void**)&pB, g_inflowB);

    cudaFuncSetAttribute(k_encoder, cudaFuncAttributeMaxDynamicSharedMemorySize, ENC_SMEM);
    cudaFuncSetAttribute(k_gat_t, cudaFuncAttributeMaxDynamicSharedMemorySize, GAT_SMEM);
    cudaFuncSetAttribute(k_gru, cudaFuncAttributeMaxDynamicSharedMemorySize, GRU_SMEM);
    cudaFuncSetAttribute(k_decoder, cudaFuncAttributeMaxDynamicSharedMemorySize, DEC_SMEM);

    k_encoder<<<512, 128, ENC_SMEM>>>(emb, feat, W_enc1, b_enc1, W_enc2, b_enc2);
    for (int l = 0; l < NL; l++) {
        k_gat_t<<<512, 128, GAT_SMEM>>>(W_gat, a_src, a_dst);
        k_gat_attn<<<NODES / 4, 512>>>(adj);
        k_gru<<<512, 128, GRU_SMEM>>>(W_z, U_z, b_z, W_r, U_r, b_r, W_c, U_c, b_c);
    }
    k_decoder<<<512, 128, DEC_SMEM>>>(W_dec1, b_dec1, W_dec2, b_dec2);
    k_normw<<<256, 256>>>(adj, demands, out_normw);

    float* cur = pA;
    float* nxt = pB;
    for (int it = 0; it < 9; it++) {
        k_flow_iter<<<256, 256>>>(adj, demands, out_normw, cur, nxt,
                                  (it == 8) ? out_pflow : nullptr);
        float* tmp = cur; cur = nxt; nxt = tmp;
    }
    cudaMemsetAsync(out_cost, 0, NB * sizeof(float), 0);
    k_flow_last<<<256, 256>>>(demands, out_normw, cur, out_flow, out_cost);
}

// round 5
// speedup vs baseline: 1.3915x; 1.3915x over previous
#include <cuda_runtime.h>
#include <math.h>

typedef unsigned long long ull;

#define NB 4
#define NV 16384
#define NK 16
#define NE 32
#define ND 64
#define NH 4
#define NL 2
#define NEGV (-1e9f)
#define NODES (NB * NV)

// ---------------- scratch ----------------
__device__ float g_h[NODES * ND];
__device__ float g_t[(size_t)NODES * NH * ND];
__device__ float g_ssrc[NODES * NH];
__device__ float g_sdst[NODES * NH];
__device__ float g_m[NODES * ND];
__device__ float g_nodew[NODES];
__device__ float g_sn[NODES];
__device__ float g_inflowA[NODES];
__device__ float g_inflowB[NODES];

__device__ __forceinline__ float sigmoidf_(float x) { return 1.0f / (1.0f + expf(-x)); }

__device__ __forceinline__ ull pack2(float x) {
    ull r; asm("mov.b64 %0, {%1, %1};" : "=l"(r) : "f"(x)); return r;
}
__device__ __forceinline__ void ffma2(ull& d, ull a, ull b) {
    asm("fma.rn.f32x2 %0, %1, %2, %0;" : "+l"(d) : "l"(a), "l"(b));
}
__device__ __forceinline__ float2 unpk(ull v) {
    float2 f; asm("mov.b64 {%0, %1}, %2;" : "=f"(f.x), "=f"(f.y) : "l"(v)); return f;
}
__device__ __forceinline__ void st4(float* p, float a, float b, float c, float d) {
    *reinterpret_cast<float4*>(p) = make_float4(a, b, c, d);
}

// stage 128 node rows of 64 floats TRANSPOSED into xs[64][128]; 256 threads, 2/row
__device__ __forceinline__ void stage_xT(const float* __restrict__ g, float* xs) {
    int r = threadIdx.x >> 1;
    int cb = (threadIdx.x & 1) * 8;
    const float4* g4 = reinterpret_cast<const float4*>(g + (size_t)r * ND);
#pragma unroll
    for (int c = cb; c < cb + 8; c++) {
        float4 v = __ldg(g4 + c);
        xs[(4 * c + 0) * 128 + r] = v.x;
        xs[(4 * c + 1) * 128 + r] = v.y;
        xs[(4 * c + 2) * 128 + r] = v.z;
        xs[(4 * c + 3) * 128 + r] = v.w;
    }
}
// load weights into smem, 256 threads
__device__ __forceinline__ void load_w(const float* __restrict__ g, float* ws, int nfloats) {
    const float4* g4 = reinterpret_cast<const float4*>(g);
    float4* s4 = reinterpret_cast<float4*>(ws);
    for (int i = threadIdx.x; i < (nfloats >> 2); i += 256) s4[i] = __ldg(g4 + i);
}

// micro-tile: 4 nodes (tn4..tn4+3) x 8 cols (tc8..tc8+7); acc[p*4+jj] = col-pair jj, node p
template <int K>
__device__ __forceinline__ void gpass(const float* __restrict__ xs, const float* __restrict__ Ws,
                                      ull acc[16], int tn4, int tc8) {
#pragma unroll 4
    for (int k = 0; k < K; k++) {
        float4 xv = *reinterpret_cast<const float4*>(xs + k * 128 + tn4);
        const ulonglong2* wp = reinterpret_cast<const ulonglong2*>(Ws + k * ND + tc8);
        ulonglong2 wa = wp[0], wb = wp[1];
        ull x0 = pack2(xv.x), x1 = pack2(xv.y), x2 = pack2(xv.z), x3 = pack2(xv.w);
#define FFP(p, xv_)                      \
    ffma2(acc[(p)*4 + 0], xv_, wa.x);    \
    ffma2(acc[(p)*4 + 1], xv_, wa.y);    \
    ffma2(acc[(p)*4 + 2], xv_, wb.x);    \
    ffma2(acc[(p)*4 + 3], xv_, wb.y);
        FFP(0, x0) FFP(1, x1) FFP(2, x2) FFP(3, x3)
#undef FFP
    }
}

__device__ __forceinline__ void acc_bias(ull acc[16], const float* __restrict__ b, int tc8) {
    const ull* bp = reinterpret_cast<const ull*>(b + tc8);
#pragma unroll
    for (int jj = 0; jj < 4; jj++) {
        ull v = __ldg(bp + jj);
        acc[0 * 4 + jj] = v; acc[1 * 4 + jj] = v; acc[2 * 4 + jj] = v; acc[3 * 4 + jj] = v;
    }
}
__device__ __forceinline__ void acc_zero(ull acc[16]) {
#pragma unroll
    for (int i = 0; i < 16; i++) acc[i] = 0ull;
}

// ---------------- encoder ----------------
#define ENC_SMEM ((34 * 128 + 64 * 128 + 34 * 64 + 64 * 64) * 4)
__global__ void __launch_bounds__(256, 2)
k_encoder(const float* __restrict__ emb, const float* __restrict__ feat,
          const float* __restrict__ W1, const float* __restrict__ b1,
          const float* __restrict__ W2, const float* __restrict__ b2) {
    extern __shared__ float sm[];
    float* xs1 = sm;                 // [34][128]
    float* xs2 = xs1 + 34 * 128;     // [64][128]
    float* W1s = xs2 + 64 * 128;     // [34][64]
    float* W2s = W1s + 34 * 64;      // [64][64]
    int tid = threadIdx.x;
    int nb0 = blockIdx.x * 128;
    int tn4 = (tid >> 3) * 4, tc8 = (tid & 7) * 8;

    {  // stage [emb|feat] transposed
        int r = tid >> 1;
        int cb = (tid & 1) * 4;
        const float4* e4 = reinterpret_cast<const float4*>(emb + (size_t)(nb0 + r) * NE);
#pragma unroll
        for (int c = cb; c < cb + 4; c++) {
            float4 v = __ldg(e4 + c);
            xs1[(4 * c + 0) * 128 + r] = v.x;
            xs1[(4 * c + 1) * 128 + r] = v.y;
            xs1[(4 * c + 2) * 128 + r] = v.z;
            xs1[(4 * c + 3) * 128 + r] = v.w;
        }
        if ((tid & 1) == 0) {
            float2 fv = __ldg(reinterpret_cast<const float2*>(feat + (size_t)(nb0 + r) * 2));
            xs1[32 * 128 + r] = fv.x;
            xs1[33 * 128 + r] = fv.y;
        }
    }
    load_w(W1, W1s, 34 * 64);
    load_w(W2, W2s, 64 * 64);
    if (tid < 128) {
        g_inflowA[nb0 + tid] = 0.0f;
        g_inflowB[nb0 + tid] = 0.0f;
    }
    __syncthreads();

    ull acc[16];
    acc_bias(acc, b1, tc8);
    gpass<34>(xs1, W1s, acc, tn4, tc8);
    // tanh -> xs2 transposed
#pragma unroll
    for (int p = 0; p < 4; p++)
#pragma unroll
        for (int jj = 0; jj < 4; jj++) {
            float2 v = unpk(acc[p * 4 + jj]);
            xs2[(tc8 + 2 * jj + 0) * 128 + tn4 + p] = tanhf(v.x);
            xs2[(tc8 + 2 * jj + 1) * 128 + tn4 + p] = tanhf(v.y);
        }
    __syncthreads();

    acc_bias(acc, b2, tc8);
    gpass<64>(xs2, W2s, acc, tn4, tc8);
#pragma unroll
    for (int p = 0; p < 4; p++) {
        float2 v0 = unpk(acc[p * 4 + 0]), v1 = unpk(acc[p * 4 + 1]);
        float2 v2 = unpk(acc[p * 4 + 2]), v3 = unpk(acc[p * 4 + 3]);
        float* row = g_h + (size_t)(nb0 + tn4 + p) * ND + tc8;
        st4(row, tanhf(v0.x), tanhf(v0.y), tanhf(v1.x), tanhf(v1.y));
        st4(row + 4, tanhf(v2.x), tanhf(v2.y), tanhf(v3.x), tanhf(v3.y));
    }
}

// ---------------- GAT transform ----------------
#define GAT_SMEM ((64 * 128 + 64 * 64) * 4)
__global__ void __launch_bounds__(256, 2)
k_gat_t(const float* __restrict__ Wgat, const float* __restrict__ asrc,
        const float* __restrict__ adst) {
    extern __shared__ float sm[];
    float* xs = sm;             // [64][128]
    float* Ws = xs + 64 * 128;  // [64][64]
    int tid = threadIdx.x;
    int nb0 = blockIdx.x * 128;
    int tn4 = (tid >> 3) * 4, tc8 = (tid & 7) * 8;
    stage_xT(g_h + (size_t)nb0 * ND, xs);

    for (int hd = 0; hd < NH; hd++) {
        __syncthreads();
        load_w(Wgat + (size_t)hd * ND * ND, Ws, ND * ND);
        __syncthreads();
        ull acc[16];
        acc_zero(acc);
        gpass<64>(xs, Ws, acc, tn4, tc8);

        float as_[8], ad_[8];
#pragma unroll
        for (int j = 0; j < 8; j++) {
            as_[j] = __ldg(&asrc[hd * ND + tc8 + j]);
            ad_[j] = __ldg(&adst[hd * ND + tc8 + j]);
        }
        float ss4[4], sd4[4];
#pragma unroll
        for (int p = 0; p < 4; p++) {
            float o[8];
            float2 v0 = unpk(acc[p * 4 + 0]), v1 = unpk(acc[p * 4 + 1]);
            float2 v2 = unpk(acc[p * 4 + 2]), v3 = unpk(acc[p * 4 + 3]);
            o[0] = v0.x; o[1] = v0.y; o[2] = v1.x; o[3] = v1.y;
            o[4] = v2.x; o[5] = v2.y; o[6] = v3.x; o[7] = v3.y;
            float s = 0.f, d = 0.f;
#pragma unroll
            for (int j = 0; j < 8; j++) { s += o[j] * as_[j]; d += o[j] * ad_[j]; }
            ss4[p] = s; sd4[p] = d;
            float* t0 = g_t + ((size_t)(nb0 + tn4 + p) * NH + hd) * ND + tc8;
            st4(t0, o[0], o[1], o[2], o[3]);
            st4(t0 + 4, o[4], o[5], o[6], o[7]);
        }
#pragma unroll
        for (int p = 0; p < 4; p++)
#pragma unroll
            for (int off = 4; off > 0; off >>= 1) {
                ss4[p] += __shfl_xor_sync(0xffffffffu, ss4[p], off);
                sd4[p] += __shfl_xor_sync(0xffffffffu, sd4[p], off);
            }
        if ((tid & 7) == 0) {
#pragma unroll
            for (int p = 0; p < 4; p++) {
                g_ssrc[(size_t)(nb0 + tn4 + p) * NH + hd] = ss4[p];
                g_sdst[(size_t)(nb0 + tn4 + p) * NH + hd] = sd4[p];
            }
        }
    }
}

// ---------------- GAT attention + aggregation ----------------
__global__ void k_gat_attn(const int* __restrict__ adj) {
    __shared__ float s_agg[4][NH][ND];
    int wid = threadIdx.x >> 5, lane = threadIdx.x & 31;
    int ni = wid >> 2, hd = wid & 3;
    int n = (blockIdx.x << 2) + ni;
    int b = n >> 14;

    float score = NEGV;
    int idx = NV;
    if (lane < NK) {
        idx = __ldg(&adj[(size_t)n * NK + lane]);
        if (idx < NV)
            score = __ldg(&g_ssrc[(size_t)n * NH + hd]) +
                    __ldg(&g_sdst[((size_t)(b << 14) + idx) * NH + hd]);
    }
    float mx = score;
#pragma unroll
    for (int o = 16; o > 0; o >>= 1) mx = fmaxf(mx, __shfl_xor_sync(0xffffffffu, mx, o));
    float e = (lane < NK) ? expf(score - mx) : 0.0f;
    float s = e;
#pragma unroll
    for (int o = 16; o > 0; o >>= 1) s += __shfl_xor_sync(0xffffffffu, s, o);
    float attn = e / s;

    float ax = 0.0f, ay = 0.0f;
#pragma unroll
    for (int k = 0; k < NK; k++) {
        int j = __shfl_sync(0xffffffffu, idx, k);
        float a = __shfl_sync(0xffffffffu, attn, k);
        if (j < NV) {
            const float2* tp =
                reinterpret_cast<const float2*>(g_t + (((size_t)(b << 14) + j) * NH + hd) * ND);
            float2 tv = __ldg(tp + lane);
            ax += a * tv.x; ay += a * tv.y;
        }
    }
    s_agg[ni][hd][2 * lane] = ax;
    s_agg[ni][hd][2 * lane + 1] = ay;
    __syncthreads();
    if (threadIdx.x < 256) {
        int nn = threadIdx.x >> 6, j = threadIdx.x & 63;
        float t = s_agg[nn][0][j] + s_agg[nn][1][j] + s_agg[nn][2][j] + s_agg[nn][3][j];
        g_m[((size_t)(blockIdx.x << 2) + nn) * ND + j] = tanhf(t * 0.25f);
    }
}

// ---------------- fused GRU (z in regs, r*h overwrites xh, combine from g_h) ----------------
#define GRU_SMEM ((2 * 64 * 128 + 64 * 64) * 4)
__global__ void __launch_bounds__(256, 2)
k_gru(const float* __restrict__ Wz, const float* __restrict__ Uz, const float* __restrict__ bz,
      const float* __restrict__ Wr, const float* __restrict__ Ur, const float* __restrict__ br,
      const float* __restrict__ Wc, const float* __restrict__ Uc, const float* __restrict__ bc) {
    extern __shared__ float sm[];
    float* xm = sm;              // [64][128]
    float* xh = sm + 64 * 128;   // [64][128], later r*h
    float* Ws = xh + 64 * 128;   // [64][64]
    int tid = threadIdx.x;
    int nb0 = blockIdx.x * 128;
    int tn4 = (tid >> 3) * 4, tc8 = (tid & 7) * 8;

    stage_xT(g_m + (size_t)nb0 * ND, xm);
    stage_xT(g_h + (size_t)nb0 * ND, xh);

    ull acc[16], zq[16];
    // ---- z (kept in registers as sigmoid) ----
    __syncthreads();
    load_w(Wz, Ws, ND * ND);
    __syncthreads();
    acc_bias(acc, bz, tc8);
    gpass<64>(xm, Ws, acc, tn4, tc8);
    __syncthreads();
    load_w(Uz, Ws, ND * ND);
    __syncthreads();
    gpass<64>(xh, Ws, acc, tn4, tc8);
#pragma unroll
    for (int i = 0; i < 16; i++) {
        float2 v = unpk(acc[i]);
        float2 o; o.x = sigmoidf_(v.x); o.y = sigmoidf_(v.y);
        ull r; asm("mov.b64 %0, {%1, %2};" : "=l"(r) : "f"(o.x), "f"(o.y));
        zq[i] = r;
    }
    // ---- r, r*h -> xh in place ----
    __syncthreads();
    load_w(Wr, Ws, ND * ND);
    __syncthreads();
    acc_bias(acc, br, tc8);
    gpass<64>(xm, Ws, acc, tn4, tc8);
    __syncthreads();
    load_w(Ur, Ws, ND * ND);
    __syncthreads();
    gpass<64>(xh, Ws, acc, tn4, tc8);
    float rh[16 * 2];
#pragma unroll
    for (int p = 0; p < 4; p++)
#pragma unroll
        for (int jj = 0; jj < 4; jj++) {
            float2 rv = unpk(acc[p * 4 + jj]);
            int c = tc8 + 2 * jj, n4 = tn4 + p;
            rh[(p * 4 + jj) * 2 + 0] = sigmoidf_(rv.x) * xh[c * 128 + n4];
            rh[(p * 4 + jj) * 2 + 1] = sigmoidf_(rv.y) * xh[(c + 1) * 128 + n4];
        }
    __syncthreads();
#pragma unroll
    for (int p = 0; p < 4; p++)
#pragma unroll
        for (int jj = 0; jj < 4; jj++) {
            int c = tc8 + 2 * jj, n4 = tn4 + p;
            xh[c * 128 + n4] = rh[(p * 4 + jj) * 2 + 0];
            xh[(c + 1) * 128 + n4] = rh[(p * 4 + jj) * 2 + 1];
        }
    // ---- c + combine ----
    __syncthreads();
    load_w(Wc, Ws, ND * ND);
    __syncthreads();
    acc_bias(acc, bc, tc8);
    gpass<64>(xm, Ws, acc, tn4, tc8);
    __syncthreads();
    load_w(Uc, Ws, ND * ND);
    __syncthreads();
    gpass<64>(xh, Ws, acc, tn4, tc8);
#pragma unroll
    for (int p = 0; p < 4; p++) {
        float* hrow = g_h + (size_t)(nb0 + tn4 + p) * ND + tc8;
        float4 ha = *reinterpret_cast<const float4*>(hrow);
        float4 hb = *reinterpret_cast<const float4*>(hrow + 4);
        float2 c0 = unpk(acc[p * 4 + 0]), c1 = unpk(acc[p * 4 + 1]);
        float2 c2 = unpk(acc[p * 4 + 2]), c3 = unpk(acc[p * 4 + 3]);
        float2 z0 = unpk(zq[p * 4 + 0]), z1 = unpk(zq[p * 4 + 1]);
        float2 z2 = unpk(zq[p * 4 + 2]), z3 = unpk(zq[p * 4 + 3]);
        st4(hrow, ha.x + z0.x * (tanhf(c0.x) - ha.x), ha.y + z0.y * (tanhf(c0.y) - ha.y),
                  ha.z + z1.x * (tanhf(c1.x) - ha.z), ha.w + z1.y * (tanhf(c1.y) - ha.w));
        st4(hrow + 4, hb.x + z2.x * (tanhf(c2.x) - hb.x), hb.y + z2.y * (tanhf(c2.y) - hb.y),
                      hb.z + z3.x * (tanhf(c3.x) - hb.z), hb.w + z3.y * (tanhf(c3.y) - hb.w));
    }
}

// ---------------- decoder ----------------
#define DEC_SMEM ((64 * 128 + 64 * 64) * 4)
__global__ void __launch_bounds__(256, 2)
k_decoder(const float* __restrict__ W1, const float* __restrict__ b1,
          const float* __restrict__ W2, const float* __restrict__ b2) {
    extern __shared__ float sm[];
    float* xs = sm;
    float* Ws = sm + 64 * 128;
    int tid = threadIdx.x;
    int nb0 = blockIdx.x * 128;
    int tn4 = (tid >> 3) * 4, tc8 = (tid & 7) * 8;
    stage_xT(g_h + (size_t)nb0 * ND, xs);
    load_w(W1, Ws, ND * ND);
    __syncthreads();
    ull acc[16];
    acc_bias(acc, b1, tc8);
    gpass<64>(xs, Ws, acc, tn4, tc8);
    float w2_[8];
#pragma unroll
    for (int j = 0; j < 8; j++) w2_[j] = __ldg(&W2[tc8 + j]);
    float pw[4];
#pragma unroll
    for (int p = 0; p < 4; p++) {
        float2 v0 = unpk(acc[p * 4 + 0]), v1 = unpk(acc[p * 4 + 1]);
        float2 v2 = unpk(acc[p * 4 + 2]), v3 = unpk(acc[p * 4 + 3]);
        pw[p] = tanhf(v0.x) * w2_[0] + tanhf(v0.y) * w2_[1] + tanhf(v1.x) * w2_[2] +
                tanhf(v1.y) * w2_[3] + tanhf(v2.x) * w2_[4] + tanhf(v2.y) * w2_[5] +
                tanhf(v3.x) * w2_[6] + tanhf(v3.y) * w2_[7];
    }
#pragma unroll
    for (int p = 0; p < 4; p++)
#pragma unroll
        for (int off = 4; off > 0; off >>= 1)
            pw[p] += __shfl_xor_sync(0xffffffffu, pw[p], off);
    if ((tid & 7) == 0) {
        float b2v = __ldg(&b2[0]);
#pragma unroll
        for (int p = 0; p < 4; p++) g_nodew[nb0 + tn4 + p] = pw[p] + b2v;
    }
}

// ---------------- edge softmax + sumsq + flow0 scatter ----------------
__global__ void k_normw(const int* __restrict__ adj, const float* __restrict__ demands,
                        float* __restrict__ out_normw) {
    int n = blockIdx.x * blockDim.x + threadIdx.x;
    int base = (n >> 14) << 14;
    int idxv[NK];
    float sc[NK];
    float mx = NEGV;
#pragma unroll
    for (int k = 0; k < NK; k++) {
        int idx = __ldg(&adj[(size_t)n * NK + k]);
        idxv[k] = idx;
        float s = (idx < NV) ? __ldg(&g_nodew[(size_t)base + idx]) : NEGV;
        sc[k] = s;
        mx = fmaxf(mx, s);
    }
    float sum = 0.0f;
#pragma unroll
    for (int k = 0; k < NK; k++) { sc[k] = expf(sc[k] - mx); sum += sc[k]; }
    float inv = 1.0f / sum;
    float nf0 = fmaxf(-__ldg(&demands[n]), 0.0f);
    float sn = 0.0f;
#pragma unroll
    for (int k = 0; k < NK; k++) {
        float nw = sc[k] * inv;
        sc[k] = nw;
        sn += nw * nw;
        out_normw[(size_t)n * NK + k] = nw;
    }
    g_sn[n] = sn;
#pragma unroll
    for (int k = 0; k < NK; k++)
        if (idxv[k] < NV) atomicAdd(&g_inflowA[base + idxv[k]], sc[k] * nf0);
}

// ---------------- fused flow iteration ----------------
__global__ void k_flow_iter(const int* __restrict__ adj, const float* __restrict__ demands,
                            const float* __restrict__ normw, float* __restrict__ cur,
                            float* __restrict__ nxt, float* __restrict__ store) {
    int n = blockIdx.x * blockDim.x + threadIdx.x;
    int base = (n >> 14) << 14;
    float nf = fmaxf(cur[n] - __ldg(&demands[n]), 0.0f);
    cur[n] = 0.0f;
#pragma unroll
    for (int k = 0; k < NK; k++) {
        int idx = __ldg(&adj[(size_t)n * NK + k]);
        float f = __ldg(&normw[(size_t)n * NK + k]) * nf;
        if (store) store[(size_t)n * NK + k] = f;
        if (idx < NV) atomicAdd(&nxt[base + idx], f);
    }
}

// ---------------- final flow + cost ----------------
__global__ void k_flow_last(const float* __restrict__ demands, const float* __restrict__ normw,
                            float* __restrict__ cur, float* __restrict__ out_flow,
                            float* __restrict__ cost) {
    int n = blockIdx.x * blockDim.x + threadIdx.x;
    int b = n >> 14;
    float nf = fmaxf(cur[n] - __ldg(&demands[n]), 0.0f);
    cur[n] = 0.0f;
    const float4* nw4 = reinterpret_cast<const float4*>(normw + (size_t)n * NK);
    float4* o4 = reinterpret_cast<float4*>(out_flow + (size_t)n * NK);
#pragma unroll
    for (int k = 0; k < 4; k++) {
        float4 v = __ldg(nw4 + k);
        v.x *= nf; v.y *= nf; v.z *= nf; v.w *= nf;
        o4[k] = v;
    }
    float val = nf * nf * __ldg(&g_sn[n]);
#pragma unroll
    for (int o = 16; o > 0; o >>= 1) val += __shfl_xor_sync(0xffffffffu, val, o);
    __shared__ float ws[8];
    if ((threadIdx.x & 31) == 0) ws[threadIdx.x >> 5] = val;
    __syncthreads();
    if (threadIdx.x == 0) {
        float t = 0.0f;
#pragma unroll
        for (int i = 0; i < 8; i++) t += ws[i];
        atomicAdd(&cost[b], t);
    }
}

// ---------------- launch ----------------
extern "C" void kernel_launch(void* const* d_in, const int* in_sizes, int n_in,
                              void* d_out, int out_size) {
    const float* emb     = (const float*)d_in[0];
    const float* feat    = (const float*)d_in[1];
    const float* demands = (const float*)d_in[2];
    const int*   adj     = (const int*)d_in[3];
    int wb = (in_sizes[5] == 1) ? 6 : 5;
    const float* W_enc1 = (const float*)d_in[wb + 0];
    const float* b_enc1 = (const float*)d_in[wb + 1];
    const float* W_enc2 = (const float*)d_in[wb + 2];
    const float* b_enc2 = (const float*)d_in[wb + 3];
    const float* W_gat  = (const float*)d_in[wb + 4];
    const float* a_src  = (const float*)d_in[wb + 5];
    const float* a_dst  = (const float*)d_in[wb + 6];
    const float* W_z    = (const float*)d_in[wb + 7];
    const float* U_z    = (const float*)d_in[wb + 8];
    const float* b_z    = (const float*)d_in[wb + 9];
    const float* W_r    = (const float*)d_in[wb + 10];
    const float* U_r    = (const float*)d_in[wb + 11];
    const float* b_r    = (const float*)d_in[wb + 12];
    const float* W_c    = (const float*)d_in[wb + 13];
    const float* U_c    = (const float*)d_in[wb + 14];
    const float* b_c    = (const float*)d_in[wb + 15];
    const float* W_dec1 = (const float*)d_in[wb + 16];
    const float* b_dec1 = (const float*)d_in[wb + 17];
    const float* W_dec2 = (const float*)d_in[wb + 18];
    const float* b_dec2 = (const float*)d_in[wb + 19];

    float* out = (float*)d_out;
    float* out_flow  = out;                               // [B,V,K] f10
    float* out_cost  = out + (size_t)NB * NV * NK;        // [B]
    float* out_normw = out_cost + NB;                     // [B,V,K]
    float* out_pflow = out_normw + (size_t)NB * NV * NK;  // [B,V,K] f9

    float *pA, *pB;
    cudaGetSymbolAddress((void**)&pA, g_inflowA);
    cudaGetSymbolAddress((void**)&pB, g_inflowB);

    cudaFuncSetAttribute(k_encoder, cudaFuncAttributeMaxDynamicSharedMemorySize, ENC_SMEM);
    cudaFuncSetAttribute(k_gat_t, cudaFuncAttributeMaxDynamicSharedMemorySize, GAT_SMEM);
    cudaFuncSetAttribute(k_gru, cudaFuncAttributeMaxDynamicSharedMemorySize, GRU_SMEM);
    cudaFuncSetAttribute(k_decoder, cudaFuncAttributeMaxDynamicSharedMemorySize, DEC_SMEM);

    k_encoder<<<512, 256, ENC_SMEM>>>(emb, feat, W_enc1, b_enc1, W_enc2, b_enc2);
    for (int l = 0; l < NL; l++) {
        k_gat_t<<<512, 256, GAT_SMEM>>>(W_gat, a_src, a_dst);
        k_gat_attn<<<NODES / 4, 512>>>(adj);
        k_gru<<<512, 256, GRU_SMEM>>>(W_z, U_z, b_z, W_r, U_r, b_r, W_c, U_c, b_c);
    }
    k_decoder<<<512, 256, DEC_SMEM>>>(W_dec1, b_dec1, W_dec2, b_dec2);
    k_normw<<<256, 256>>>(adj, demands, out_normw);

    float* cur = pA;
    float* nxt = pB;
    for (int it = 0; it < 9; it++) {
        k_flow_iter<<<256, 256>>>(adj, demands, out_normw, cur, nxt,
                                  (it == 8) ? out_pflow : nullptr);
        float* tmp = cur; cur = nxt; nxt = tmp;
    }
    cudaMemsetAsync(out_cost, 0, NB * sizeof(float), 0);
    k_flow_last<<<256, 256>>>(demands, out_normw, cur, out_flow, out_cost);
}

// round 6
// speedup vs baseline: 1.4952x; 1.0745x over previous
#include <cuda_runtime.h>
#include <math.h>

typedef unsigned long long ull;

#define NB 4
#define NV 16384
#define NK 16
#define NE 32
#define ND 64
#define NH 4
#define NL 2
#define NEGV (-1e9f)
#define NODES (NB * NV)

// ---------------- scratch ----------------
__device__ float g_h[NODES * ND];
__device__ float g_t[(size_t)NODES * NH * ND];
__device__ float g_zscr[NODES * ND];
__device__ float g_ssrc[NODES * NH];
__device__ float g_sdst[NODES * NH];
__device__ float g_m[NODES * ND];
__device__ float g_nodew[NODES];
__device__ float g_sn[NODES];
__device__ float g_inflowA[NODES];
__device__ float g_inflowB[NODES];
__device__ unsigned g_barc;

__device__ __forceinline__ float sigmoidf_(float x) { return 1.0f / (1.0f + expf(-x)); }

__device__ __forceinline__ ull pack2(float x) {
    ull r; asm("mov.b64 %0, {%1, %1};" : "=l"(r) : "f"(x)); return r;
}
__device__ __forceinline__ ull packf2(float a, float b) {
    ull r; asm("mov.b64 %0, {%1, %2};" : "=l"(r) : "f"(a), "f"(b)); return r;
}
__device__ __forceinline__ void ffma2(ull& d, ull a, ull b) {
    asm("fma.rn.f32x2 %0, %1, %2, %0;" : "+l"(d) : "l"(a), "l"(b));
}
__device__ __forceinline__ float2 unpk(ull v) {
    float2 f; asm("mov.b64 {%0, %1}, %2;" : "=f"(f.x), "=f"(f.y) : "l"(v)); return f;
}
__device__ __forceinline__ void st4(float* p, float a, float b, float c, float d) {
    *reinterpret_cast<float4*>(p) = make_float4(a, b, c, d);
}

// stage 128 node rows of 64 floats TRANSPOSED into xs[64][128] (128 threads, thread = node)
__device__ __forceinline__ void stage_xT(const float* __restrict__ g, float* xs) {
    int tid = threadIdx.x;
    const float4* g4 = reinterpret_cast<const float4*>(g + (size_t)tid * ND);
#pragma unroll
    for (int c = 0; c < 16; c++) {
        float4 v = __ldg(g4 + c);
        xs[(4 * c + 0) * 128 + tid] = v.x;
        xs[(4 * c + 1) * 128 + tid] = v.y;
        xs[(4 * c + 2) * 128 + tid] = v.z;
        xs[(4 * c + 3) * 128 + tid] = v.w;
    }
}
// load weights into smem, 128 threads
__device__ __forceinline__ void load_w(const float* __restrict__ g, float* ws, int nfloats) {
    const float4* g4 = reinterpret_cast<const float4*>(g);
    float4* s4 = reinterpret_cast<float4*>(ws);
    for (int i = threadIdx.x; i < (nfloats >> 2); i += 128) s4[i] = __ldg(g4 + i);
}

// register-tiled pass: acc[j*4+p] (col tc8+j, node-pair p) += xs^T @ Ws (smem W)
template <int K>
__device__ __forceinline__ void gpass(const float* __restrict__ xs, const float* __restrict__ Ws,
                                      ull acc[32], int tn8, int tc8) {
#pragma unroll 4
    for (int k = 0; k < K; k++) {
        const ulonglong2* xr = reinterpret_cast<const ulonglong2*>(xs + k * 128 + tn8);
        ulonglong2 xa = xr[0], xb = xr[1];
        const float4* wr = reinterpret_cast<const float4*>(Ws + k * ND + tc8);
        float4 wa = wr[0], wb = wr[1];
        ull w0 = pack2(wa.x), w1 = pack2(wa.y), w2 = pack2(wa.z), w3 = pack2(wa.w);
        ull w4 = pack2(wb.x), w5 = pack2(wb.y), w6 = pack2(wb.z), w7 = pack2(wb.w);
#define FFJ(j, wv)                    \
    ffma2(acc[(j)*4 + 0], wv, xa.x);  \
    ffma2(acc[(j)*4 + 1], wv, xa.y);  \
    ffma2(acc[(j)*4 + 2], wv, xb.x);  \
    ffma2(acc[(j)*4 + 3], wv, xb.y);
        FFJ(0, w0) FFJ(1, w1) FFJ(2, w2) FFJ(3, w3)
        FFJ(4, w4) FFJ(5, w5) FFJ(6, w6) FFJ(7, w7)
#undef FFJ
    }
}

// K=64 GEMM in two k-halves through an 8KB W half-buffer
__device__ __forceinline__ void mm2(const float* __restrict__ xs, const float* __restrict__ Wg,
                                    float* Ws, ull acc[32], int tn8, int tc8) {
    __syncthreads();                  // previous Ws readers done
    load_w(Wg, Ws, 32 * ND);
    __syncthreads();
    gpass<32>(xs, Ws, acc, tn8, tc8);
    __syncthreads();
    load_w(Wg + 32 * ND, Ws, 32 * ND);
    __syncthreads();
    gpass<32>(xs + 32 * 128, Ws, acc, tn8, tc8);
}

__device__ __forceinline__ void acc_bias(ull acc[32], const float* __restrict__ b, int tc8) {
#pragma unroll
    for (int j = 0; j < 8; j++) {
        ull v = pack2(__ldg(&b[tc8 + j]));
        acc[j * 4 + 0] = v; acc[j * 4 + 1] = v; acc[j * 4 + 2] = v; acc[j * 4 + 3] = v;
    }
}
__device__ __forceinline__ void acc_zero(ull acc[32]) {
#pragma unroll
    for (int i = 0; i < 32; i++) acc[i] = 0ull;
}

// ---------------- encoder ----------------
#define ENC_SMEM ((34 * 128 + 64 * 128 + 64 * 64) * 4)
__global__ void __launch_bounds__(128, 3)
k_encoder(const float* __restrict__ emb, const float* __restrict__ feat,
          const float* __restrict__ W1, const float* __restrict__ b1,
          const float* __restrict__ W2, const float* __restrict__ b2) {
    extern __shared__ float sm[];
    float* xs1 = sm;                 // [34][128]
    float* xs2 = sm + 34 * 128;      // [64][128]
    float* Ws = xs2 + 64 * 128;      // [64][64] shared sequentially
    int tid = threadIdx.x;
    int nb0 = blockIdx.x * 128;
    int tn8 = (tid >> 3) * 8, tc8 = (tid & 7) * 8;

    {
        const float4* e4 = reinterpret_cast<const float4*>(emb + (size_t)(nb0 + tid) * NE);
#pragma unroll
        for (int c = 0; c < 8; c++) {
            float4 v = __ldg(e4 + c);
            xs1[(4 * c + 0) * 128 + tid] = v.x;
            xs1[(4 * c + 1) * 128 + tid] = v.y;
            xs1[(4 * c + 2) * 128 + tid] = v.z;
            xs1[(4 * c + 3) * 128 + tid] = v.w;
        }
        float2 fv = __ldg(reinterpret_cast<const float2*>(feat + (size_t)(nb0 + tid) * 2));
        xs1[32 * 128 + tid] = fv.x;
        xs1[33 * 128 + tid] = fv.y;
    }
    load_w(W1, Ws, 34 * ND);
    g_inflowA[nb0 + tid] = 0.0f;
    g_inflowB[nb0 + tid] = 0.0f;
    __syncthreads();

    ull acc[32];
    acc_bias(acc, b1, tc8);
    gpass<34>(xs1, Ws, acc, tn8, tc8);
#pragma unroll
    for (int j = 0; j < 8; j++)
#pragma unroll
        for (int p = 0; p < 4; p++) {
            float2 v = unpk(acc[j * 4 + p]);
            *reinterpret_cast<ull*>(xs2 + (tc8 + j) * 128 + tn8 + 2 * p) =
                packf2(tanhf(v.x), tanhf(v.y));
        }
    __syncthreads();
    load_w(W2, Ws, ND * ND);
    __syncthreads();

    acc_bias(acc, b2, tc8);
    gpass<64>(xs2, Ws, acc, tn8, tc8);
#pragma unroll
    for (int p = 0; p < 4; p++) {
        float o0[8], o1[8];
#pragma unroll
        for (int j = 0; j < 8; j++) {
            float2 v = unpk(acc[j * 4 + p]);
            o0[j] = tanhf(v.x); o1[j] = tanhf(v.y);
        }
        float* r0 = g_h + (size_t)(nb0 + tn8 + 2 * p) * ND + tc8;
        st4(r0, o0[0], o0[1], o0[2], o0[3]); st4(r0 + 4, o0[4], o0[5], o0[6], o0[7]);
        float* r1 = r0 + ND;
        st4(r1, o1[0], o1[1], o1[2], o1[3]); st4(r1 + 4, o1[4], o1[5], o1[6], o1[7]);
    }
}

// ---------------- GAT transform ----------------
#define GAT_SMEM ((64 * 128 + 64 * 64) * 4)
__global__ void __launch_bounds__(128, 3)
k_gat_t(const float* __restrict__ Wgat, const float* __restrict__ asrc,
        const float* __restrict__ adst) {
    extern __shared__ float sm[];
    float* xs = sm;             // [64][128]
    float* Ws = sm + 64 * 128;  // [64][64]
    int tid = threadIdx.x;
    int nb0 = blockIdx.x * 128;
    int tn8 = (tid >> 3) * 8, tc8 = (tid & 7) * 8;
    stage_xT(g_h + (size_t)nb0 * ND, xs);

    for (int hd = 0; hd < NH; hd++) {
        __syncthreads();
        load_w(Wgat + (size_t)hd * ND * ND, Ws, ND * ND);
        __syncthreads();
        ull acc[32];
        acc_zero(acc);
        gpass<64>(xs, Ws, acc, tn8, tc8);

        float as_[8], ad_[8];
#pragma unroll
        for (int j = 0; j < 8; j++) {
            as_[j] = __ldg(&asrc[hd * ND + tc8 + j]);
            ad_[j] = __ldg(&adst[hd * ND + tc8 + j]);
        }
        float ss8[8], sd8[8];
#pragma unroll
        for (int p = 0; p < 4; p++) {
            float o0[8], o1[8];
            float s0 = 0.f, s1 = 0.f, d0 = 0.f, d1 = 0.f;
#pragma unroll
            for (int j = 0; j < 8; j++) {
                float2 v = unpk(acc[j * 4 + p]);
                o0[j] = v.x; o1[j] = v.y;
                s0 += v.x * as_[j]; d0 += v.x * ad_[j];
                s1 += v.y * as_[j]; d1 += v.y * ad_[j];
            }
            float* t0 = g_t + ((size_t)(nb0 + tn8 + 2 * p) * NH + hd) * ND + tc8;
            st4(t0, o0[0], o0[1], o0[2], o0[3]); st4(t0 + 4, o0[4], o0[5], o0[6], o0[7]);
            float* t1 = t0 + NH * ND;
            st4(t1, o1[0], o1[1], o1[2], o1[3]); st4(t1 + 4, o1[4], o1[5], o1[6], o1[7]);
            ss8[2 * p] = s0; ss8[2 * p + 1] = s1;
            sd8[2 * p] = d0; sd8[2 * p + 1] = d1;
        }
#pragma unroll
        for (int q = 0; q < 8; q++) {
#pragma unroll
            for (int off = 4; off > 0; off >>= 1) {
                ss8[q] += __shfl_xor_sync(0xffffffffu, ss8[q], off);
                sd8[q] += __shfl_xor_sync(0xffffffffu, sd8[q], off);
            }
        }
        if ((tid & 7) == 0) {
#pragma unroll
            for (int q = 0; q < 8; q++) {
                g_ssrc[(size_t)(nb0 + tn8 + q) * NH + hd] = ss8[q];
                g_sdst[(size_t)(nb0 + tn8 + q) * NH + hd] = sd8[q];
            }
        }
    }
}

// ---------------- GAT attention + aggregation ----------------
__global__ void k_gat_attn(const int* __restrict__ adj) {
    __shared__ float s_agg[4][NH][ND];
    int wid = threadIdx.x >> 5, lane = threadIdx.x & 31;
    int ni = wid >> 2, hd = wid & 3;
    int n = (blockIdx.x << 2) + ni;
    int b = n >> 14;

    float score = NEGV;
    int idx = NV;
    if (lane < NK) {
        idx = __ldg(&adj[(size_t)n * NK + lane]);
        if (idx < NV)
            score = __ldg(&g_ssrc[(size_t)n * NH + hd]) +
                    __ldg(&g_sdst[((size_t)(b << 14) + idx) * NH + hd]);
    }
    float mx = score;
#pragma unroll
    for (int o = 16; o > 0; o >>= 1) mx = fmaxf(mx, __shfl_xor_sync(0xffffffffu, mx, o));
    float e = (lane < NK) ? expf(score - mx) : 0.0f;
    float s = e;
#pragma unroll
    for (int o = 16; o > 0; o >>= 1) s += __shfl_xor_sync(0xffffffffu, s, o);
    float attn = e / s;

    float ax = 0.0f, ay = 0.0f;
#pragma unroll
    for (int k = 0; k < NK; k++) {
        int j = __shfl_sync(0xffffffffu, idx, k);
        float a = __shfl_sync(0xffffffffu, attn, k);
        if (j < NV) {
            const float2* tp =
                reinterpret_cast<const float2*>(g_t + (((size_t)(b << 14) + j) * NH + hd) * ND);
            float2 tv = __ldg(tp + lane);
            ax += a * tv.x; ay += a * tv.y;
        }
    }
    s_agg[ni][hd][2 * lane] = ax;
    s_agg[ni][hd][2 * lane + 1] = ay;
    __syncthreads();
    if (threadIdx.x < 256) {
        int nn = threadIdx.x >> 6, j = threadIdx.x & 63;
        float t = s_agg[nn][0][j] + s_agg[nn][1][j] + s_agg[nn][2][j] + s_agg[nn][3][j];
        g_m[((size_t)(blockIdx.x << 2) + nn) * ND + j] = tanhf(t * 0.25f);
    }
}

// ---------------- fused GRU (z -> scratch, r*h overwrites xh, combine from g_h) ----------------
#define GRU_SMEM ((2 * 64 * 128 + 32 * 64) * 4)
__global__ void __launch_bounds__(128, 3)
k_gru(const float* __restrict__ Wz, const float* __restrict__ Uz, const float* __restrict__ bz,
      const float* __restrict__ Wr, const float* __restrict__ Ur, const float* __restrict__ br,
      const float* __restrict__ Wc, const float* __restrict__ Uc, const float* __restrict__ bc) {
    extern __shared__ float sm[];
    float* xm = sm;              // [64][128]
    float* xh = sm + 64 * 128;   // [64][128], later holds r*h
    float* Ws = xh + 64 * 128;   // [32][64] half-buffer
    int tid = threadIdx.x;
    int nb0 = blockIdx.x * 128;
    int tn8 = (tid >> 3) * 8, tc8 = (tid & 7) * 8;

    stage_xT(g_m + (size_t)nb0 * ND, xm);
    stage_xT(g_h + (size_t)nb0 * ND, xh);

    ull acc[32];
    // ---- z -> global scratch ----
    acc_bias(acc, bz, tc8);
    mm2(xm, Wz, Ws, acc, tn8, tc8);
    mm2(xh, Uz, Ws, acc, tn8, tc8);
#pragma unroll
    for (int p = 0; p < 4; p++) {
        float o0[8], o1[8];
#pragma unroll
        for (int j = 0; j < 8; j++) {
            float2 v = unpk(acc[j * 4 + p]);
            o0[j] = sigmoidf_(v.x); o1[j] = sigmoidf_(v.y);
        }
        float* r0 = g_zscr + (size_t)(nb0 + tn8 + 2 * p) * ND + tc8;
        st4(r0, o0[0], o0[1], o0[2], o0[3]); st4(r0 + 4, o0[4], o0[5], o0[6], o0[7]);
        float* r1 = r0 + ND;
        st4(r1, o1[0], o1[1], o1[2], o1[3]); st4(r1 + 4, o1[4], o1[5], o1[6], o1[7]);
    }
    // ---- r, r*h -> xh in place ----
    acc_bias(acc, br, tc8);
    mm2(xm, Wr, Ws, acc, tn8, tc8);
    mm2(xh, Ur, Ws, acc, tn8, tc8);
    ull rh[32];
#pragma unroll
    for (int j = 0; j < 8; j++)
#pragma unroll
        for (int p = 0; p < 4; p++) {
            float2 rv = unpk(acc[j * 4 + p]);
            float2 hv = unpk(*reinterpret_cast<const ull*>(xh + (tc8 + j) * 128 + tn8 + 2 * p));
            rh[j * 4 + p] = packf2(sigmoidf_(rv.x) * hv.x, sigmoidf_(rv.y) * hv.y);
        }
    __syncthreads();
#pragma unroll
    for (int j = 0; j < 8; j++)
#pragma unroll
        for (int p = 0; p < 4; p++)
            *reinterpret_cast<ull*>(xh + (tc8 + j) * 128 + tn8 + 2 * p) = rh[j * 4 + p];
    // ---- c + combine ----
    acc_bias(acc, bc, tc8);
    mm2(xm, Wc, Ws, acc, tn8, tc8);
    mm2(xh, Uc, Ws, acc, tn8, tc8);
#pragma unroll
    for (int p = 0; p < 4; p++) {
        float* hr0 = g_h + (size_t)(nb0 + tn8 + 2 * p) * ND + tc8;
        float* hr1 = hr0 + ND;
        const float* zr0 = g_zscr + (size_t)(nb0 + tn8 + 2 * p) * ND + tc8;
        const float* zr1 = zr0 + ND;
        float4 h0a = *reinterpret_cast<const float4*>(hr0);
        float4 h0b = *reinterpret_cast<const float4*>(hr0 + 4);
        float4 h1a = *reinterpret_cast<const float4*>(hr1);
        float4 h1b = *reinterpret_cast<const float4*>(hr1 + 4);
        float4 z0a = __ldg(reinterpret_cast<const float4*>(zr0));
        float4 z0b = __ldg(reinterpret_cast<const float4*>(zr0 + 4));
        float4 z1a = __ldg(reinterpret_cast<const float4*>(zr1));
        float4 z1b = __ldg(reinterpret_cast<const float4*>(zr1 + 4));
        float c0[8], c1[8];
#pragma unroll
        for (int j = 0; j < 8; j++) {
            float2 v = unpk(acc[j * 4 + p]);
            c0[j] = tanhf(v.x); c1[j] = tanhf(v.y);
        }
        st4(hr0, h0a.x + z0a.x * (c0[0] - h0a.x), h0a.y + z0a.y * (c0[1] - h0a.y),
                 h0a.z + z0a.z * (c0[2] - h0a.z), h0a.w + z0a.w * (c0[3] - h0a.w));
        st4(hr0 + 4, h0b.x + z0b.x * (c0[4] - h0b.x), h0b.y + z0b.y * (c0[5] - h0b.y),
                     h0b.z + z0b.z * (c0[6] - h0b.z), h0b.w + z0b.w * (c0[7] - h0b.w));
        st4(hr1, h1a.x + z1a.x * (c1[0] - h1a.x), h1a.y + z1a.y * (c1[1] - h1a.y),
                 h1a.z + z1a.z * (c1[2] - h1a.z), h1a.w + z1a.w * (c1[3] - h1a.w));
        st4(hr1 + 4, h1b.x + z1b.x * (c1[4] - h1b.x), h1b.y + z1b.y * (c1[5] - h1b.y),
                     h1b.z + z1b.z * (c1[6] - h1b.z), h1b.w + z1b.w * (c1[7] - h1b.w));
    }
}

// ---------------- decoder ----------------
#define DEC_SMEM ((64 * 128 + 64 * 64) * 4)
__global__ void __launch_bounds__(128, 3)
k_decoder(const float* __restrict__ W1, const float* __restrict__ b1,
          const float* __restrict__ W2, const float* __restrict__ b2) {
    extern __shared__ float sm[];
    float* xs = sm;
    float* Ws = sm + 64 * 128;
    int tid = threadIdx.x;
    int nb0 = blockIdx.x * 128;
    int tn8 = (tid >> 3) * 8, tc8 = (tid & 7) * 8;
    stage_xT(g_h + (size_t)nb0 * ND, xs);
    load_w(W1, Ws, ND * ND);
    __syncthreads();
    ull acc[32];
    acc_bias(acc, b1, tc8);
    gpass<64>(xs, Ws, acc, tn8, tc8);
    float w2_[8];
#pragma unroll
    for (int j = 0; j < 8; j++) w2_[j] = __ldg(&W2[tc8 + j]);
    float pw[8];
#pragma unroll
    for (int p = 0; p < 4; p++) {
        float s0 = 0.f, s1 = 0.f;
#pragma unroll
        for (int j = 0; j < 8; j++) {
            float2 v = unpk(acc[j * 4 + p]);
            s0 += tanhf(v.x) * w2_[j];
            s1 += tanhf(v.y) * w2_[j];
        }
        pw[2 * p] = s0; pw[2 * p + 1] = s1;
    }
#pragma unroll
    for (int q = 0; q < 8; q++)
#pragma unroll
        for (int off = 4; off > 0; off >>= 1)
            pw[q] += __shfl_xor_sync(0xffffffffu, pw[q], off);
    if ((tid & 7) == 0) {
        float b2v = __ldg(&b2[0]);
#pragma unroll
        for (int q = 0; q < 8; q++) g_nodew[nb0 + tn8 + q] = pw[q] + b2v;
    }
}

// ---------------- edge softmax + sumsq + flow0 scatter ----------------
__global__ void k_normw(const int* __restrict__ adj, const float* __restrict__ demands,
                        float* __restrict__ out_normw) {
    int n = blockIdx.x * blockDim.x + threadIdx.x;
    int base = (n >> 14) << 14;
    int idxv[NK];
    float sc[NK];
    float mx = NEGV;
#pragma unroll
    for (int k = 0; k < NK; k++) {
        int idx = __ldg(&adj[(size_t)n * NK + k]);
        idxv[k] = idx;
        float s = (idx < NV) ? __ldg(&g_nodew[(size_t)base + idx]) : NEGV;
        sc[k] = s;
        mx = fmaxf(mx, s);
    }
    float sum = 0.0f;
#pragma unroll
    for (int k = 0; k < NK; k++) { sc[k] = expf(sc[k] - mx); sum += sc[k]; }
    float inv = 1.0f / sum;
    float nf0 = fmaxf(-__ldg(&demands[n]), 0.0f);
    float sn = 0.0f;
#pragma unroll
    for (int k = 0; k < NK; k++) {
        float nw = sc[k] * inv;
        sc[k] = nw;
        sn += nw * nw;
        out_normw[(size_t)n * NK + k] = nw;
    }
    g_sn[n] = sn;
#pragma unroll
    for (int k = 0; k < NK; k++)
        if (idxv[k] < NV) atomicAdd(&g_inflowA[base + idxv[k]], sc[k] * nf0);
}

// ---------------- fused 10-iteration flow solver (persistent, software grid barrier) ----------------
__global__ void __launch_bounds__(256)
k_flow_all(const int* __restrict__ adj, const float* __restrict__ demands,
           const float* __restrict__ normw, float* bufA, float* bufB,
           float* __restrict__ out_flow, float* __restrict__ out_pflow,
           float* __restrict__ cost) {
    int n = blockIdx.x * 256 + threadIdx.x;
    int base = (n >> 14) << 14;
    int idxv[NK];
#pragma unroll
    for (int k = 0; k < NK; k++) idxv[k] = __ldg(&adj[(size_t)n * NK + k]);
    float nw[NK];
    const float4* nw4 = reinterpret_cast<const float4*>(normw + (size_t)n * NK);
#pragma unroll
    for (int k = 0; k < 4; k++) {
        float4 v = __ldg(nw4 + k);
        nw[4 * k] = v.x; nw[4 * k + 1] = v.y; nw[4 * k + 2] = v.z; nw[4 * k + 3] = v.w;
    }
    float dem = __ldg(&demands[n]);
    float* cur = bufA;
    float* nxt = bufB;
    for (int it = 0; it < 9; it++) {
        float inval = __ldcg(&cur[n]);  // atomics bypass L1 -> read from L2
        float nf = fmaxf(inval - dem, 0.0f);
        cur[n] = 0.0f;
        if (it == 8) {
            float4* o4 = reinterpret_cast<float4*>(out_pflow + (size_t)n * NK);
#pragma unroll
            for (int k = 0; k < 4; k++)
                o4[k] = make_float4(nw[4 * k] * nf, nw[4 * k + 1] * nf,
                                    nw[4 * k + 2] * nf, nw[4 * k + 3] * nf);
        }
#pragma unroll
        for (int k = 0; k < NK; k++)
            if (idxv[k] < NV) atomicAdd(&nxt[base + idxv[k]], nw[k] * nf);
        // grid barrier
        __syncthreads();
        if (threadIdx.x == 0) {
            __threadfence();
            atomicAdd(&g_barc, 1u);
            unsigned tgt = (unsigned)(it + 1) * gridDim.x;
            while (*((volatile unsigned*)&g_barc) < tgt) {}
            __threadfence();
        }
        __syncthreads();
        float* t = cur; cur = nxt; nxt = t;
    }
    float nf = fmaxf(__ldcg(&cur[n]) - dem, 0.0f);
    {
        float4* o4 = reinterpret_cast<float4*>(out_flow + (size_t)n * NK);
#pragma unroll
        for (int k = 0; k < 4; k++)
            o4[k] = make_float4(nw[4 * k] * nf, nw[4 * k + 1] * nf,
                                nw[4 * k + 2] * nf, nw[4 * k + 3] * nf);
    }
    float val = nf * nf * __ldg(&g_sn[n]);
#pragma unroll
    for (int o = 16; o > 0; o >>= 1) val += __shfl_xor_sync(0xffffffffu, val, o);
    __shared__ float wsum[8];
    if ((threadIdx.x & 31) == 0) wsum[threadIdx.x >> 5] = val;
    __syncthreads();
    if (threadIdx.x == 0) {
        float t = 0.0f;
#pragma unroll
        for (int i = 0; i < 8; i++) t += wsum[i];
        atomicAdd(&cost[n >> 14], t);
    }
}

// ---------------- launch ----------------
extern "C" void kernel_launch(void* const* d_in, const int* in_sizes, int n_in,
                              void* d_out, int out_size) {
    const float* emb     = (const float*)d_in[0];
    const float* feat    = (const float*)d_in[1];
    const float* demands = (const float*)d_in[2];
    const int*   adj     = (const int*)d_in[3];
    int wb = (in_sizes[5] == 1) ? 6 : 5;
    const float* W_enc1 = (const float*)d_in[wb + 0];
    const float* b_enc1 = (const float*)d_in[wb + 1];
    const float* W_enc2 = (const float*)d_in[wb + 2];
    const float* b_enc2 = (const float*)d_in[wb + 3];
    const float* W_gat  = (const float*)d_in[wb + 4];
    const float* a_src  = (const float*)d_in[wb + 5];
    const float* a_dst  = (const float*)d_in[wb + 6];
    const float* W_z    = (const float*)d_in[wb + 7];
    const float* U_z    = (const float*)d_in[wb + 8];
    const float* b_z    = (const float*)d_in[wb + 9];
    const float* W_r    = (const float*)d_in[wb + 10];
    const float* U_r    = (const float*)d_in[wb + 11];
    const float* b_r    = (const float*)d_in[wb + 12];
    const float* W_c    = (const float*)d_in[wb + 13];
    const float* U_c    = (const float*)d_in[wb + 14];
    const float* b_c    = (const float*)d_in[wb + 15];
    const float* W_dec1 = (const float*)d_in[wb + 16];
    const float* b_dec1 = (const float*)d_in[wb + 17];
    const float* W_dec2 = (const float*)d_in[wb + 18];
    const float* b_dec2 = (const float*)d_in[wb + 19];

    float* out = (float*)d_out;
    float* out_flow  = out;                               // [B,V,K] f10
    float* out_cost  = out + (size_t)NB * NV * NK;        // [B]
    float* out_normw = out_cost + NB;                     // [B,V,K]
    float* out_pflow = out_normw + (size_t)NB * NV * NK;  // [B,V,K] f9

    float *pA, *pB;
    cudaGetSymbolAddress((void**)&pA, g_inflowA);
    cudaGetSymbolAddress((void**)&pB, g_inflowB);
    unsigned* pbar;
    cudaGetSymbolAddress((void**)&pbar, g_barc);

    cudaFuncSetAttribute(k_encoder, cudaFuncAttributeMaxDynamicSharedMemorySize, ENC_SMEM);
    cudaFuncSetAttribute(k_gat_t, cudaFuncAttributeMaxDynamicSharedMemorySize, GAT_SMEM);
    cudaFuncSetAttribute(k_gru, cudaFuncAttributeMaxDynamicSharedMemorySize, GRU_SMEM);
    cudaFuncSetAttribute(k_decoder, cudaFuncAttributeMaxDynamicSharedMemorySize, DEC_SMEM);

    k_encoder<<<512, 128, ENC_SMEM>>>(emb, feat, W_enc1, b_enc1, W_enc2, b_enc2);
    for (int l = 0; l < NL; l++) {
        k_gat_t<<<512, 128, GAT_SMEM>>>(W_gat, a_src, a_dst);
        k_gat_attn<<<NODES / 4, 512>>>(adj);
        k_gru<<<512, 128, GRU_SMEM>>>(W_z, U_z, b_z, W_r, U_r, b_r, W_c, U_c, b_c);
    }
    k_decoder<<<512, 128, DEC_SMEM>>>(W_dec1, b_dec1, W_dec2, b_dec2);
    k_normw<<<256, 256>>>(adj, demands, out_normw);

    cudaMemsetAsync(pbar, 0, sizeof(unsigned), 0);
    cudaMemsetAsync(out_cost, 0, NB * sizeof(float), 0);
    k_flow_all<<<256, 256>>>(adj, demands, out_normw, pA, pB, out_flow, out_pflow, out_cost);
}